// round 5
// baseline (speedup 1.0000x reference)
#include <cuda_runtime.h>
#include <math.h>

// x (64, 40, 64, 500) f32 -> per (b,f): cov 64x64, eigh (parallel Jacobi), logm, triu -> (64,40,2080)
// One block per matrix. Symmetric fused two-sided Jacobi A-update (process k1<=k2
// blocks only, mirror-store transpose), hoisted per-lane rotation params,
// transposed float2-vectorized eigenvector updates.

#define C 64
#define TLEN 500
#define NMAT 2560
#define NTRI 2080
#define LDA 65          // stride for sA
#define LDV 66          // stride for sVt (even -> float2-aligned rows)
#define NSWEEPS 6
#define THREADS 256

__global__ __launch_bounds__(THREADS, 4)
void spd_logm_kernel(const float* __restrict__ xin, float* __restrict__ out)
{
    __shared__ float  sA[C * LDA];        // covariance -> diagonalized -> W
    __shared__ float  sVt[C * LDV];       // eigenvectors TRANSPOSED (row j = eigvec j)
    __shared__ float2 scs[32];            // (c, s) per pair
    __shared__ int    spq[32];            // p | (q<<8)
    __shared__ float  ssum[C];
    __shared__ float  slam[C];

    const int tid = threadIdx.x;
    const int mat = blockIdx.x;
    const float* __restrict__ xm = xin + (size_t)mat * (C * TLEN);
    float* __restrict__ om = out + (size_t)mat * NTRI;

    // ---------------- Phase 1: covariance ----------------
    {
        float* xt = sVt;                // 64 x 32 tile, stride 33
        const int ty = tid >> 4;
        const int tx = tid & 15;
        float acc[4][4];
#pragma unroll
        for (int i = 0; i < 4; i++)
#pragma unroll
            for (int j = 0; j < 4; j++) acc[i][j] = 0.0f;
        float rowsum = 0.0f;

        for (int t0 = 0; t0 < TLEN; t0 += 32) {
#pragma unroll
            for (int it = 0; it < 8; it++) {
                int e = tid + it * THREADS;
                int r = e >> 5, cc = e & 31;
                int t = t0 + cc;
                xt[r * 33 + cc] = (t < TLEN) ? xm[r * TLEN + t] : 0.0f;
            }
            __syncthreads();
            if (tid < C) {
#pragma unroll
                for (int cc = 0; cc < 32; cc++) rowsum += xt[tid * 33 + cc];
            }
#pragma unroll 4
            for (int tt = 0; tt < 32; tt++) {
                float a0 = xt[(4 * ty + 0) * 33 + tt];
                float a1 = xt[(4 * ty + 1) * 33 + tt];
                float a2 = xt[(4 * ty + 2) * 33 + tt];
                float a3 = xt[(4 * ty + 3) * 33 + tt];
                float b0 = xt[(4 * tx + 0) * 33 + tt];
                float b1 = xt[(4 * tx + 1) * 33 + tt];
                float b2 = xt[(4 * tx + 2) * 33 + tt];
                float b3 = xt[(4 * tx + 3) * 33 + tt];
                acc[0][0] += a0 * b0; acc[0][1] += a0 * b1; acc[0][2] += a0 * b2; acc[0][3] += a0 * b3;
                acc[1][0] += a1 * b0; acc[1][1] += a1 * b1; acc[1][2] += a1 * b2; acc[1][3] += a1 * b3;
                acc[2][0] += a2 * b0; acc[2][1] += a2 * b1; acc[2][2] += a2 * b2; acc[2][3] += a2 * b3;
                acc[3][0] += a3 * b0; acc[3][1] += a3 * b1; acc[3][2] += a3 * b2; acc[3][3] += a3 * b3;
            }
            __syncthreads();
        }
        if (tid < C) ssum[tid] = rowsum;
        __syncthreads();

        const float invT  = 1.0f / (float)TLEN;
        const float invT1 = 1.0f / (float)(TLEN - 1);
#pragma unroll
        for (int i = 0; i < 4; i++) {
            float si = ssum[4 * ty + i];
#pragma unroll
            for (int j = 0; j < 4; j++) {
                float sj = ssum[4 * tx + j];
                sA[(4 * ty + i) * LDA + (4 * tx + j)] =
                    (acc[i][j] - si * sj * invT) * invT1;
            }
        }
    }
    __syncthreads();

    // Vt = I
#pragma unroll
    for (int it = 0; it < 16; it++) {
        int e = tid + it * THREADS;
        int i = e >> 6, j = e & 63;
        sVt[i * LDV + j] = (i == j) ? 1.0f : 0.0f;
    }
    __syncthreads();

    const int k2h = tid & 31;          // this thread's fixed column-pair id

    // ---------------- Phase 2: parallel cyclic Jacobi ----------------
    for (int sweep = 0; sweep < NSWEEPS; sweep++) {
        for (int r = 0; r < 63; r++) {
            if (tid < 32) {
                int p, q;
                if (tid == 0) { p = 63; q = r % 63; }
                else {
                    p = (r + tid) % 63;
                    q = (r - tid + 63) % 63;
                }
                float app = sA[p * LDA + p];
                float aqq = sA[q * LDA + q];
                float apq = sA[p * LDA + q];
                float cc, ss;
                if (fabsf(apq) > 1e-36f) {
                    float theta = (aqq - app) / (2.0f * apq);
                    float t = copysignf(1.0f, theta) /
                              (fabsf(theta) + sqrtf(theta * theta + 1.0f));
                    cc = rsqrtf(t * t + 1.0f);
                    ss = t * cc;
                } else { cc = 1.0f; ss = 0.0f; }
                scs[tid] = make_float2(cc, ss);
                spq[tid] = p | (q << 8);
            }
            __syncthreads();

            // Hoisted per-lane params (invariant across the 4 block iterations)
            {
                const int    pq2 = spq[k2h];
                const float2 cs2 = scs[k2h];
                const int p2 = pq2 & 255, q2 = pq2 >> 8;

                // A' = J^T A J, symmetric: only blocks k1 <= k2, mirror-store transpose.
#pragma unroll
                for (int it = 0; it < 4; it++) {
                    int k1 = (tid >> 5) + it * 8;
                    if (k1 <= k2h) {
                        int    pq1 = spq[k1];      // warp-broadcast
                        float2 cs1 = scs[k1];
                        int p1 = pq1 & 255, q1 = pq1 >> 8;
                        float a00 = sA[p1 * LDA + p2], a01 = sA[p1 * LDA + q2];
                        float a10 = sA[q1 * LDA + p2], a11 = sA[q1 * LDA + q2];
                        float t00 = cs1.x * a00 - cs1.y * a10, t01 = cs1.x * a01 - cs1.y * a11;
                        float t10 = cs1.y * a00 + cs1.x * a10, t11 = cs1.y * a01 + cs1.x * a11;
                        float b00 = cs2.x * t00 - cs2.y * t01, b01 = cs2.y * t00 + cs2.x * t01;
                        float b10 = cs2.x * t10 - cs2.y * t11, b11 = cs2.y * t10 + cs2.x * t11;
                        sA[p1 * LDA + p2] = b00; sA[p1 * LDA + q2] = b01;
                        sA[q1 * LDA + p2] = b10; sA[q1 * LDA + q2] = b11;
                        if (k1 < k2h) {            // mirror (transpose) block
                            sA[p2 * LDA + p1] = b00; sA[q2 * LDA + p1] = b01;
                            sA[p2 * LDA + q1] = b10; sA[q2 * LDA + q1] = b11;
                        }
                    }
                }
            }
            // Vt rows p,q: float2-vectorized (params warp-broadcast)
#pragma unroll
            for (int it = 0; it < 4; it++) {
                int e = tid + it * THREADS;       // 0..1023
                int k = e >> 5, i2 = e & 31;
                int pq = spq[k];
                float2 cs = scs[k];
                int p = pq & 255, q = pq >> 8;
                float2* vp2 = (float2*)&sVt[p * LDV];
                float2* vq2 = (float2*)&sVt[q * LDV];
                float2 vp = vp2[i2], vq = vq2[i2];
                float2 np, nq;
                np.x = cs.x * vp.x - cs.y * vq.x;
                np.y = cs.x * vp.y - cs.y * vq.y;
                nq.x = cs.y * vp.x + cs.x * vq.x;
                nq.y = cs.y * vp.y + cs.x * vq.y;
                vp2[i2] = np;
                vq2[i2] = nq;
            }
            __syncthreads();
        }
    }

    // ---------------- Phase 3: log-eigenvalues + reconstruction ----------------
    if (tid < C) {
        float lam = sA[tid * LDA + tid];
        lam = fmaxf(lam, 1e-10f);
        slam[tid] = logf(lam);
    }
    __syncthreads();
    // W[e][i] = Vt[e][i] * log(lam[e])
#pragma unroll
    for (int it = 0; it < 16; it++) {
        int e2 = tid + it * THREADS;
        int e = e2 >> 6, i = e2 & 63;
        sA[e * LDA + i] = sVt[e * LDV + i] * slam[e];
    }
    __syncthreads();

    // logm[i][j] = sum_e W[e][i] * Vt[e][j], upper triangle only
#pragma unroll
    for (int it = 0; it < 16; it++) {
        int e2 = tid + it * THREADS;
        int i = e2 >> 6, j = e2 & 63;
        if (i <= j) {
            float dot = 0.0f;
#pragma unroll
            for (int e = 0; e < C; e++)
                dot += sA[e * LDA + i] * sVt[e * LDV + j];
            int o = i * C - ((i * (i - 1)) >> 1) + (j - i);
            om[o] = dot;
        }
    }
}

extern "C" void kernel_launch(void* const* d_in, const int* in_sizes, int n_in,
                              void* d_out, int out_size)
{
    const float* x = (const float*)d_in[0];
    float* out = (float*)d_out;
    spd_logm_kernel<<<NMAT, THREADS>>>(x, out);
}

// round 11
// speedup vs baseline: 1.1045x; 1.1045x over previous
#include <cuda_runtime.h>
#include <math.h>

// x (64, 40, 64, 500) f32 -> per (b,f): cov 64x64, eigh (parallel Jacobi), logm, triu -> (64,40,2080)
// One block per matrix. Fused two-sided Jacobi A-update (all 1024 2x2 blocks),
// hoisted per-lane rotation params, transposed float2-vectorized eigenvector updates.
// NSWEEPS=6 is the convergence floor (5 sweeps -> rel_err 2.5e-3 FAIL).

#define C 64
#define TLEN 500
#define NMAT 2560
#define NTRI 2080
#define LDA 65          // stride for sA
#define LDV 66          // stride for sVt (even -> float2-aligned rows)
#define NSWEEPS 6
#define THREADS 256

__global__ __launch_bounds__(THREADS, 4)
void spd_logm_kernel(const float* __restrict__ xin, float* __restrict__ out)
{
    __shared__ float  sA[C * LDA];        // covariance -> diagonalized -> W
    __shared__ float  sVt[C * LDV];       // eigenvectors TRANSPOSED (row j = eigvec j)
    __shared__ float2 scs[32];            // (c, s) per pair
    __shared__ int    spq[32];            // p | (q<<8)
    __shared__ float  ssum[C];
    __shared__ float  slam[C];

    const int tid = threadIdx.x;
    const int mat = blockIdx.x;
    const float* __restrict__ xm = xin + (size_t)mat * (C * TLEN);
    float* __restrict__ om = out + (size_t)mat * NTRI;

    // ---------------- Phase 1: covariance ----------------
    {
        float* xt = sVt;                // 64 x 32 tile, stride 33
        const int ty = tid >> 4;
        const int tx = tid & 15;
        float acc[4][4];
#pragma unroll
        for (int i = 0; i < 4; i++)
#pragma unroll
            for (int j = 0; j < 4; j++) acc[i][j] = 0.0f;
        float rowsum = 0.0f;

        for (int t0 = 0; t0 < TLEN; t0 += 32) {
#pragma unroll
            for (int it = 0; it < 8; it++) {
                int e = tid + it * THREADS;
                int r = e >> 5, cc = e & 31;
                int t = t0 + cc;
                xt[r * 33 + cc] = (t < TLEN) ? xm[r * TLEN + t] : 0.0f;
            }
            __syncthreads();
            if (tid < C) {
#pragma unroll
                for (int cc = 0; cc < 32; cc++) rowsum += xt[tid * 33 + cc];
            }
#pragma unroll 4
            for (int tt = 0; tt < 32; tt++) {
                float a0 = xt[(4 * ty + 0) * 33 + tt];
                float a1 = xt[(4 * ty + 1) * 33 + tt];
                float a2 = xt[(4 * ty + 2) * 33 + tt];
                float a3 = xt[(4 * ty + 3) * 33 + tt];
                float b0 = xt[(4 * tx + 0) * 33 + tt];
                float b1 = xt[(4 * tx + 1) * 33 + tt];
                float b2 = xt[(4 * tx + 2) * 33 + tt];
                float b3 = xt[(4 * tx + 3) * 33 + tt];
                acc[0][0] += a0 * b0; acc[0][1] += a0 * b1; acc[0][2] += a0 * b2; acc[0][3] += a0 * b3;
                acc[1][0] += a1 * b0; acc[1][1] += a1 * b1; acc[1][2] += a1 * b2; acc[1][3] += a1 * b3;
                acc[2][0] += a2 * b0; acc[2][1] += a2 * b1; acc[2][2] += a2 * b2; acc[2][3] += a2 * b3;
                acc[3][0] += a3 * b0; acc[3][1] += a3 * b1; acc[3][2] += a3 * b2; acc[3][3] += a3 * b3;
            }
            __syncthreads();
        }
        if (tid < C) ssum[tid] = rowsum;
        __syncthreads();

        const float invT  = 1.0f / (float)TLEN;
        const float invT1 = 1.0f / (float)(TLEN - 1);
#pragma unroll
        for (int i = 0; i < 4; i++) {
            float si = ssum[4 * ty + i];
#pragma unroll
            for (int j = 0; j < 4; j++) {
                float sj = ssum[4 * tx + j];
                sA[(4 * ty + i) * LDA + (4 * tx + j)] =
                    (acc[i][j] - si * sj * invT) * invT1;
            }
        }
    }
    __syncthreads();

    // Vt = I
#pragma unroll
    for (int it = 0; it < 16; it++) {
        int e = tid + it * THREADS;
        int i = e >> 6, j = e & 63;
        sVt[i * LDV + j] = (i == j) ? 1.0f : 0.0f;
    }
    __syncthreads();

    const int k2h = tid & 31;          // this thread's fixed column-pair id

    // ---------------- Phase 2: parallel cyclic Jacobi ----------------
    for (int sweep = 0; sweep < NSWEEPS; sweep++) {
        for (int r = 0; r < 63; r++) {
            if (tid < 32) {
                int p, q;
                if (tid == 0) { p = 63; q = r % 63; }
                else {
                    p = (r + tid) % 63;
                    q = (r - tid + 63) % 63;
                }
                float app = sA[p * LDA + p];
                float aqq = sA[q * LDA + q];
                float apq = sA[p * LDA + q];
                float cc, ss;
                if (fabsf(apq) > 1e-36f) {
                    float theta = (aqq - app) / (2.0f * apq);
                    float t = copysignf(1.0f, theta) /
                              (fabsf(theta) + sqrtf(theta * theta + 1.0f));
                    cc = rsqrtf(t * t + 1.0f);
                    ss = t * cc;
                } else { cc = 1.0f; ss = 0.0f; }
                scs[tid] = make_float2(cc, ss);
                spq[tid] = p | (q << 8);
            }
            __syncthreads();

            // Fused A' = J^T A J: all 1024 2x2 blocks, per-lane params hoisted.
            {
                const int    pq2 = spq[k2h];
                const float2 cs2 = scs[k2h];
                const int p2 = pq2 & 255, q2 = pq2 >> 8;
#pragma unroll
                for (int it = 0; it < 4; it++) {
                    int k1 = (tid >> 5) + it * 8;     // warp-uniform
                    int    pq1 = spq[k1];             // broadcast
                    float2 cs1 = scs[k1];
                    int p1 = pq1 & 255, q1 = pq1 >> 8;
                    float a00 = sA[p1 * LDA + p2], a01 = sA[p1 * LDA + q2];
                    float a10 = sA[q1 * LDA + p2], a11 = sA[q1 * LDA + q2];
                    float t00 = cs1.x * a00 - cs1.y * a10, t01 = cs1.x * a01 - cs1.y * a11;
                    float t10 = cs1.y * a00 + cs1.x * a10, t11 = cs1.y * a01 + cs1.x * a11;
                    sA[p1 * LDA + p2] = cs2.x * t00 - cs2.y * t01;
                    sA[p1 * LDA + q2] = cs2.y * t00 + cs2.x * t01;
                    sA[q1 * LDA + p2] = cs2.x * t10 - cs2.y * t11;
                    sA[q1 * LDA + q2] = cs2.y * t10 + cs2.x * t11;
                }
            }
            // Vt rows p,q: float2-vectorized (params warp-broadcast)
#pragma unroll
            for (int it = 0; it < 4; it++) {
                int e = tid + it * THREADS;       // 0..1023
                int k = e >> 5, i2 = e & 31;
                int pq = spq[k];
                float2 cs = scs[k];
                int p = pq & 255, q = pq >> 8;
                float2* vp2 = (float2*)&sVt[p * LDV];
                float2* vq2 = (float2*)&sVt[q * LDV];
                float2 vp = vp2[i2], vq = vq2[i2];
                float2 np, nq;
                np.x = cs.x * vp.x - cs.y * vq.x;
                np.y = cs.x * vp.y - cs.y * vq.y;
                nq.x = cs.y * vp.x + cs.x * vq.x;
                nq.y = cs.y * vp.y + cs.x * vq.y;
                vp2[i2] = np;
                vq2[i2] = nq;
            }
            __syncthreads();
        }
    }

    // ---------------- Phase 3: log-eigenvalues + reconstruction ----------------
    if (tid < C) {
        float lam = sA[tid * LDA + tid];
        lam = fmaxf(lam, 1e-10f);
        slam[tid] = logf(lam);
    }
    __syncthreads();
    // W[e][i] = Vt[e][i] * log(lam[e])
#pragma unroll
    for (int it = 0; it < 16; it++) {
        int e2 = tid + it * THREADS;
        int e = e2 >> 6, i = e2 & 63;
        sA[e * LDA + i] = sVt[e * LDV + i] * slam[e];
    }
    __syncthreads();

    // logm[i][j] = sum_e W[e][i] * Vt[e][j], upper triangle only
#pragma unroll
    for (int it = 0; it < 16; it++) {
        int e2 = tid + it * THREADS;
        int i = e2 >> 6, j = e2 & 63;
        if (i <= j) {
            float dot = 0.0f;
#pragma unroll
            for (int e = 0; e < C; e++)
                dot += sA[e * LDA + i] * sVt[e * LDV + j];
            int o = i * C - ((i * (i - 1)) >> 1) + (j - i);
            om[o] = dot;
        }
    }
}

extern "C" void kernel_launch(void* const* d_in, const int* in_sizes, int n_in,
                              void* d_out, int out_size)
{
    const float* x = (const float*)d_in[0];
    float* out = (float*)d_out;
    spd_logm_kernel<<<NMAT, THREADS>>>(x, out);
}

// round 12
// speedup vs baseline: 1.2927x; 1.1704x over previous
#include <cuda_runtime.h>
#include <math.h>

// x (64, 40, 64, 500) f32 -> per (b,f): cov 64x64, eigh (parallel Jacobi), logm, triu -> (64,40,2080)
// One block per matrix. R3 structure (2944us baseline) + bank-balanced pair labeling:
// a prep kernel orients each round's 32 pairs so that the 32 "p" indices are distinct
// mod 32 (always possible: degree-2 residue multigraph = disjoint cycles), making every
// A-phase shared load/store bank-conflict-free. NSWEEPS=6 is the convergence floor.

#define C 64
#define TLEN 500
#define NMAT 2560
#define NTRI 2080
#define LDA 65          // stride for sA  (65 % 32 == 1 -> bank = (p1+p2)%32)
#define LDV 66          // stride for sVt (even -> float2-aligned rows)
#define NSWEEPS 6
#define THREADS 256

// Bank-balanced (p,q) labels per round: p | (q<<8)
__device__ int g_pq[63][32];

__global__ void prep_pairs_kernel()
{
    int r = threadIdx.x;
    if (r >= 63) return;

    int A[32], B[32];
    A[0] = 63; B[0] = r % 63;
    for (int t = 1; t < 32; t++) {
        A[t] = (r + t) % 63;
        B[t] = (r - t + 63) % 63;
    }
    // incidence of the 32 edges on 32 residue-vertices (each vertex degree exactly 2)
    int inc[32][2];
    int cnt[32];
    for (int v = 0; v < 32; v++) cnt[v] = 0;
    for (int k = 0; k < 32; k++) {
        int u = A[k] & 31, v = B[k] & 31;
        inc[u][cnt[u]++] = k;
        inc[v][cnt[v]++] = k;
    }
    // orient each cycle consistently: every residue becomes the "p"-side exactly once
    bool done[32];
    for (int k = 0; k < 32; k++) done[k] = false;
    for (int k0 = 0; k0 < 32; k0++) {
        if (done[k0]) continue;
        int e = k0;
        int u = A[e] & 31;
        while (!done[e]) {
            done[e] = true;
            int p, q;
            if ((A[e] & 31) == u) { p = A[e]; q = B[e]; }
            else                  { p = B[e]; q = A[e]; }
            g_pq[r][e] = p | (q << 8);
            int v = q & 31;
            int e2 = (inc[v][0] == e) ? inc[v][1] : inc[v][0];
            e = e2;
            u = v;
        }
    }
}

__global__ __launch_bounds__(THREADS, 4)
void spd_logm_kernel(const float* __restrict__ xin, float* __restrict__ out)
{
    __shared__ float  sA[C * LDA];        // covariance -> diagonalized -> W
    __shared__ float  sVt[C * LDV];       // eigenvectors TRANSPOSED (row j = eigvec j)
    __shared__ float2 scs[32];            // (c, s) per pair
    __shared__ int    spq[32];            // p | (q<<8)
    __shared__ float  ssum[C];
    __shared__ float  slam[C];

    const int tid = threadIdx.x;
    const int mat = blockIdx.x;
    const float* __restrict__ xm = xin + (size_t)mat * (C * TLEN);
    float* __restrict__ om = out + (size_t)mat * NTRI;

    // ---------------- Phase 1: covariance ----------------
    {
        float* xt = sVt;                // 64 x 32 tile, stride 33
        const int ty = tid >> 4;
        const int tx = tid & 15;
        float acc[4][4];
#pragma unroll
        for (int i = 0; i < 4; i++)
#pragma unroll
            for (int j = 0; j < 4; j++) acc[i][j] = 0.0f;
        float rowsum = 0.0f;

        for (int t0 = 0; t0 < TLEN; t0 += 32) {
#pragma unroll
            for (int it = 0; it < 8; it++) {
                int e = tid + it * THREADS;
                int r = e >> 5, cc = e & 31;
                int t = t0 + cc;
                xt[r * 33 + cc] = (t < TLEN) ? xm[r * TLEN + t] : 0.0f;
            }
            __syncthreads();
            if (tid < C) {
#pragma unroll
                for (int cc = 0; cc < 32; cc++) rowsum += xt[tid * 33 + cc];
            }
#pragma unroll 4
            for (int tt = 0; tt < 32; tt++) {
                float a0 = xt[(4 * ty + 0) * 33 + tt];
                float a1 = xt[(4 * ty + 1) * 33 + tt];
                float a2 = xt[(4 * ty + 2) * 33 + tt];
                float a3 = xt[(4 * ty + 3) * 33 + tt];
                float b0 = xt[(4 * tx + 0) * 33 + tt];
                float b1 = xt[(4 * tx + 1) * 33 + tt];
                float b2 = xt[(4 * tx + 2) * 33 + tt];
                float b3 = xt[(4 * tx + 3) * 33 + tt];
                acc[0][0] += a0 * b0; acc[0][1] += a0 * b1; acc[0][2] += a0 * b2; acc[0][3] += a0 * b3;
                acc[1][0] += a1 * b0; acc[1][1] += a1 * b1; acc[1][2] += a1 * b2; acc[1][3] += a1 * b3;
                acc[2][0] += a2 * b0; acc[2][1] += a2 * b1; acc[2][2] += a2 * b2; acc[2][3] += a2 * b3;
                acc[3][0] += a3 * b0; acc[3][1] += a3 * b1; acc[3][2] += a3 * b2; acc[3][3] += a3 * b3;
            }
            __syncthreads();
        }
        if (tid < C) ssum[tid] = rowsum;
        __syncthreads();

        const float invT  = 1.0f / (float)TLEN;
        const float invT1 = 1.0f / (float)(TLEN - 1);
#pragma unroll
        for (int i = 0; i < 4; i++) {
            float si = ssum[4 * ty + i];
#pragma unroll
            for (int j = 0; j < 4; j++) {
                float sj = ssum[4 * tx + j];
                sA[(4 * ty + i) * LDA + (4 * tx + j)] =
                    (acc[i][j] - si * sj * invT) * invT1;
            }
        }
    }
    __syncthreads();

    // Vt = I
#pragma unroll
    for (int it = 0; it < 16; it++) {
        int e = tid + it * THREADS;
        int i = e >> 6, j = e & 63;
        sVt[i * LDV + j] = (i == j) ? 1.0f : 0.0f;
    }
    __syncthreads();

    // ---------------- Phase 2: parallel cyclic Jacobi ----------------
    for (int sweep = 0; sweep < NSWEEPS; sweep++) {
        for (int r = 0; r < 63; r++) {
            if (tid < 32) {
                int pqt = g_pq[r][tid];            // bank-balanced labeling
                int p = pqt & 255, q = pqt >> 8;
                float app = sA[p * LDA + p];
                float aqq = sA[q * LDA + q];
                float apq = sA[p * LDA + q];
                float cc, ss;
                if (fabsf(apq) > 1e-36f) {
                    float theta = (aqq - app) / (2.0f * apq);
                    float t = copysignf(1.0f, theta) /
                              (fabsf(theta) + sqrtf(theta * theta + 1.0f));
                    cc = rsqrtf(t * t + 1.0f);
                    ss = t * cc;
                } else { cc = 1.0f; ss = 0.0f; }
                scs[tid] = make_float2(cc, ss);
                spq[tid] = pqt;
            }
            __syncthreads();

            // Fused A' = J^T A J: all 1024 2x2 blocks; loads/stores conflict-free
            // because {p2 mod 32} and {q2 mod 32} are permutations of 0..31.
#pragma unroll
            for (int it = 0; it < 4; it++) {
                int e = tid + it * THREADS;       // 0..1023
                int k1 = e >> 5, k2 = e & 31;
                int pq1 = spq[k1], pq2 = spq[k2];
                float2 cs1 = scs[k1], cs2 = scs[k2];
                int p1 = pq1 & 255, q1 = pq1 >> 8;
                int p2 = pq2 & 255, q2 = pq2 >> 8;
                float a00 = sA[p1 * LDA + p2], a01 = sA[p1 * LDA + q2];
                float a10 = sA[q1 * LDA + p2], a11 = sA[q1 * LDA + q2];
                float t00 = cs1.x * a00 - cs1.y * a10, t01 = cs1.x * a01 - cs1.y * a11;
                float t10 = cs1.y * a00 + cs1.x * a10, t11 = cs1.y * a01 + cs1.x * a11;
                sA[p1 * LDA + p2] = cs2.x * t00 - cs2.y * t01;
                sA[p1 * LDA + q2] = cs2.y * t00 + cs2.x * t01;
                sA[q1 * LDA + p2] = cs2.x * t10 - cs2.y * t11;
                sA[q1 * LDA + q2] = cs2.y * t10 + cs2.x * t11;
            }
            // Vt rows p,q: float2-vectorized (rows contiguous -> conflict-free)
#pragma unroll
            for (int it = 0; it < 4; it++) {
                int e = tid + it * THREADS;       // 0..1023
                int k = e >> 5, i2 = e & 31;
                int pq = spq[k];
                float2 cs = scs[k];
                int p = pq & 255, q = pq >> 8;
                float2* vp2 = (float2*)&sVt[p * LDV];
                float2* vq2 = (float2*)&sVt[q * LDV];
                float2 vp = vp2[i2], vq = vq2[i2];
                float2 np, nq;
                np.x = cs.x * vp.x - cs.y * vq.x;
                np.y = cs.x * vp.y - cs.y * vq.y;
                nq.x = cs.y * vp.x + cs.x * vq.x;
                nq.y = cs.y * vp.y + cs.x * vq.y;
                vp2[i2] = np;
                vq2[i2] = nq;
            }
            __syncthreads();
        }
    }

    // ---------------- Phase 3: log-eigenvalues + reconstruction ----------------
    if (tid < C) {
        float lam = sA[tid * LDA + tid];
        lam = fmaxf(lam, 1e-10f);
        slam[tid] = logf(lam);
    }
    __syncthreads();
    // W[e][i] = Vt[e][i] * log(lam[e])
#pragma unroll
    for (int it = 0; it < 16; it++) {
        int e2 = tid + it * THREADS;
        int e = e2 >> 6, i = e2 & 63;
        sA[e * LDA + i] = sVt[e * LDV + i] * slam[e];
    }
    __syncthreads();

    // logm[i][j] = sum_e W[e][i] * Vt[e][j], upper triangle only
#pragma unroll
    for (int it = 0; it < 16; it++) {
        int e2 = tid + it * THREADS;
        int i = e2 >> 6, j = e2 & 63;
        if (i <= j) {
            float dot = 0.0f;
#pragma unroll
            for (int e = 0; e < C; e++)
                dot += sA[e * LDA + i] * sVt[e * LDV + j];
            int o = i * C - ((i * (i - 1)) >> 1) + (j - i);
            om[o] = dot;
        }
    }
}

extern "C" void kernel_launch(void* const* d_in, const int* in_sizes, int n_in,
                              void* d_out, int out_size)
{
    const float* x = (const float*)d_in[0];
    float* out = (float*)d_out;
    prep_pairs_kernel<<<1, 64>>>();
    spd_logm_kernel<<<NMAT, THREADS>>>(x, out);
}

// round 13
// speedup vs baseline: 1.3110x; 1.0142x over previous
#include <cuda_runtime.h>
#include <math.h>

// x (64, 40, 64, 500) f32 -> per (b,f): cov 64x64, eigh (parallel Jacobi), logm, triu -> (64,40,2080)
// One block per matrix. Bank-balanced pair labeling (prep kernel orients each round's
// pairs so all 32 "p" indices are distinct mod 32 -> conflict-free A-phase).
// NSWEEPS=6 is the convergence floor. This round: occupancy 4->5 blocks/SM via
// __launch_bounds__(256,5) (regs 64 -> <=51) to fill crossbar latency bubbles.

#define C 64
#define TLEN 500
#define NMAT 2560
#define NTRI 2080
#define LDA 65          // stride for sA  (65 % 32 == 1 -> bank = (p1+p2)%32)
#define LDV 66          // stride for sVt (even -> float2-aligned rows)
#define NSWEEPS 6
#define THREADS 256

// Bank-balanced (p,q) labels per round: p | (q<<8)
__device__ int g_pq[63][32];

__global__ void prep_pairs_kernel()
{
    int r = threadIdx.x;
    if (r >= 63) return;

    int A[32], B[32];
    A[0] = 63; B[0] = r % 63;
    for (int t = 1; t < 32; t++) {
        A[t] = (r + t) % 63;
        B[t] = (r - t + 63) % 63;
    }
    // incidence of the 32 edges on 32 residue-vertices (each vertex degree exactly 2)
    int inc[32][2];
    int cnt[32];
    for (int v = 0; v < 32; v++) cnt[v] = 0;
    for (int k = 0; k < 32; k++) {
        int u = A[k] & 31, v = B[k] & 31;
        inc[u][cnt[u]++] = k;
        inc[v][cnt[v]++] = k;
    }
    // orient each cycle consistently: every residue becomes the "p"-side exactly once
    bool done[32];
    for (int k = 0; k < 32; k++) done[k] = false;
    for (int k0 = 0; k0 < 32; k0++) {
        if (done[k0]) continue;
        int e = k0;
        int u = A[e] & 31;
        while (!done[e]) {
            done[e] = true;
            int p, q;
            if ((A[e] & 31) == u) { p = A[e]; q = B[e]; }
            else                  { p = B[e]; q = A[e]; }
            g_pq[r][e] = p | (q << 8);
            int v = q & 31;
            int e2 = (inc[v][0] == e) ? inc[v][1] : inc[v][0];
            e = e2;
            u = v;
        }
    }
}

__global__ __launch_bounds__(THREADS, 5)
void spd_logm_kernel(const float* __restrict__ xin, float* __restrict__ out)
{
    __shared__ float  sA[C * LDA];        // covariance -> diagonalized -> W
    __shared__ float  sVt[C * LDV];       // eigenvectors TRANSPOSED (row j = eigvec j)
    __shared__ float2 scs[32];            // (c, s) per pair
    __shared__ int    spq[32];            // p | (q<<8)
    __shared__ float  ssum[C];
    __shared__ float  slam[C];

    const int tid = threadIdx.x;
    const int mat = blockIdx.x;
    const float* __restrict__ xm = xin + (size_t)mat * (C * TLEN);
    float* __restrict__ om = out + (size_t)mat * NTRI;

    // ---------------- Phase 1: covariance ----------------
    {
        float* xt = sVt;                // 64 x 32 tile, stride 33
        const int ty = tid >> 4;
        const int tx = tid & 15;
        float acc[4][4];
#pragma unroll
        for (int i = 0; i < 4; i++)
#pragma unroll
            for (int j = 0; j < 4; j++) acc[i][j] = 0.0f;
        float rowsum = 0.0f;

        for (int t0 = 0; t0 < TLEN; t0 += 32) {
#pragma unroll
            for (int it = 0; it < 8; it++) {
                int e = tid + it * THREADS;
                int r = e >> 5, cc = e & 31;
                int t = t0 + cc;
                xt[r * 33 + cc] = (t < TLEN) ? xm[r * TLEN + t] : 0.0f;
            }
            __syncthreads();
            if (tid < C) {
#pragma unroll
                for (int cc = 0; cc < 32; cc++) rowsum += xt[tid * 33 + cc];
            }
#pragma unroll 4
            for (int tt = 0; tt < 32; tt++) {
                float a0 = xt[(4 * ty + 0) * 33 + tt];
                float a1 = xt[(4 * ty + 1) * 33 + tt];
                float a2 = xt[(4 * ty + 2) * 33 + tt];
                float a3 = xt[(4 * ty + 3) * 33 + tt];
                float b0 = xt[(4 * tx + 0) * 33 + tt];
                float b1 = xt[(4 * tx + 1) * 33 + tt];
                float b2 = xt[(4 * tx + 2) * 33 + tt];
                float b3 = xt[(4 * tx + 3) * 33 + tt];
                acc[0][0] += a0 * b0; acc[0][1] += a0 * b1; acc[0][2] += a0 * b2; acc[0][3] += a0 * b3;
                acc[1][0] += a1 * b0; acc[1][1] += a1 * b1; acc[1][2] += a1 * b2; acc[1][3] += a1 * b3;
                acc[2][0] += a2 * b0; acc[2][1] += a2 * b1; acc[2][2] += a2 * b2; acc[2][3] += a2 * b3;
                acc[3][0] += a3 * b0; acc[3][1] += a3 * b1; acc[3][2] += a3 * b2; acc[3][3] += a3 * b3;
            }
            __syncthreads();
        }
        if (tid < C) ssum[tid] = rowsum;
        __syncthreads();

        const float invT  = 1.0f / (float)TLEN;
        const float invT1 = 1.0f / (float)(TLEN - 1);
#pragma unroll
        for (int i = 0; i < 4; i++) {
            float si = ssum[4 * ty + i];
#pragma unroll
            for (int j = 0; j < 4; j++) {
                float sj = ssum[4 * tx + j];
                sA[(4 * ty + i) * LDA + (4 * tx + j)] =
                    (acc[i][j] - si * sj * invT) * invT1;
            }
        }
    }
    __syncthreads();

    // Vt = I
#pragma unroll
    for (int it = 0; it < 16; it++) {
        int e = tid + it * THREADS;
        int i = e >> 6, j = e & 63;
        sVt[i * LDV + j] = (i == j) ? 1.0f : 0.0f;
    }
    __syncthreads();

    // ---------------- Phase 2: parallel cyclic Jacobi ----------------
    for (int sweep = 0; sweep < NSWEEPS; sweep++) {
        for (int r = 0; r < 63; r++) {
            if (tid < 32) {
                int pqt = g_pq[r][tid];            // bank-balanced labeling
                int p = pqt & 255, q = pqt >> 8;
                float app = sA[p * LDA + p];
                float aqq = sA[q * LDA + q];
                float apq = sA[p * LDA + q];
                float cc, ss;
                if (fabsf(apq) > 1e-36f) {
                    float theta = (aqq - app) / (2.0f * apq);
                    float t = copysignf(1.0f, theta) /
                              (fabsf(theta) + sqrtf(theta * theta + 1.0f));
                    cc = rsqrtf(t * t + 1.0f);
                    ss = t * cc;
                } else { cc = 1.0f; ss = 0.0f; }
                scs[tid] = make_float2(cc, ss);
                spq[tid] = pqt;
            }
            __syncthreads();

            // Fused A' = J^T A J: all 1024 2x2 blocks; loads/stores conflict-free
            // because {p2 mod 32} and {q2 mod 32} are permutations of 0..31.
#pragma unroll
            for (int it = 0; it < 4; it++) {
                int e = tid + it * THREADS;       // 0..1023
                int k1 = e >> 5, k2 = e & 31;
                int pq1 = spq[k1], pq2 = spq[k2];
                float2 cs1 = scs[k1], cs2 = scs[k2];
                int p1 = pq1 & 255, q1 = pq1 >> 8;
                int p2 = pq2 & 255, q2 = pq2 >> 8;
                float a00 = sA[p1 * LDA + p2], a01 = sA[p1 * LDA + q2];
                float a10 = sA[q1 * LDA + p2], a11 = sA[q1 * LDA + q2];
                float t00 = cs1.x * a00 - cs1.y * a10, t01 = cs1.x * a01 - cs1.y * a11;
                float t10 = cs1.y * a00 + cs1.x * a10, t11 = cs1.y * a01 + cs1.x * a11;
                sA[p1 * LDA + p2] = cs2.x * t00 - cs2.y * t01;
                sA[p1 * LDA + q2] = cs2.y * t00 + cs2.x * t01;
                sA[q1 * LDA + p2] = cs2.x * t10 - cs2.y * t11;
                sA[q1 * LDA + q2] = cs2.y * t10 + cs2.x * t11;
            }
            // Vt rows p,q: float2-vectorized (rows contiguous -> conflict-free)
#pragma unroll
            for (int it = 0; it < 4; it++) {
                int e = tid + it * THREADS;       // 0..1023
                int k = e >> 5, i2 = e & 31;
                int pq = spq[k];
                float2 cs = scs[k];
                int p = pq & 255, q = pq >> 8;
                float2* vp2 = (float2*)&sVt[p * LDV];
                float2* vq2 = (float2*)&sVt[q * LDV];
                float2 vp = vp2[i2], vq = vq2[i2];
                float2 np, nq;
                np.x = cs.x * vp.x - cs.y * vq.x;
                np.y = cs.x * vp.y - cs.y * vq.y;
                nq.x = cs.y * vp.x + cs.x * vq.x;
                nq.y = cs.y * vp.y + cs.x * vq.y;
                vp2[i2] = np;
                vq2[i2] = nq;
            }
            __syncthreads();
        }
    }

    // ---------------- Phase 3: log-eigenvalues + reconstruction ----------------
    if (tid < C) {
        float lam = sA[tid * LDA + tid];
        lam = fmaxf(lam, 1e-10f);
        slam[tid] = logf(lam);
    }
    __syncthreads();
    // W[e][i] = Vt[e][i] * log(lam[e])
#pragma unroll
    for (int it = 0; it < 16; it++) {
        int e2 = tid + it * THREADS;
        int e = e2 >> 6, i = e2 & 63;
        sA[e * LDA + i] = sVt[e * LDV + i] * slam[e];
    }
    __syncthreads();

    // logm[i][j] = sum_e W[e][i] * Vt[e][j], upper triangle only
#pragma unroll
    for (int it = 0; it < 16; it++) {
        int e2 = tid + it * THREADS;
        int i = e2 >> 6, j = e2 & 63;
        if (i <= j) {
            float dot = 0.0f;
#pragma unroll
            for (int e = 0; e < C; e++)
                dot += sA[e * LDA + i] * sVt[e * LDV + j];
            int o = i * C - ((i * (i - 1)) >> 1) + (j - i);
            om[o] = dot;
        }
    }
}

extern "C" void kernel_launch(void* const* d_in, const int* in_sizes, int n_in,
                              void* d_out, int out_size)
{
    const float* x = (const float*)d_in[0];
    float* out = (float*)d_out;
    prep_pairs_kernel<<<1, 64>>>();
    spd_logm_kernel<<<NMAT, THREADS>>>(x, out);
}

// round 14
// speedup vs baseline: 1.3258x; 1.0112x over previous
#include <cuda_runtime.h>
#include <math.h>

// x (64, 40, 64, 500) f32 -> per (b,f): cov 64x64, eigh (parallel Jacobi), logm, triu -> (64,40,2080)
// One block per matrix. Bank-balanced pair labeling (conflict-free A-phase).
// This round: float4-packed rotation params {c,s,p,q} (1 LDS.128 broadcast instead of 4
// loads), merged A+V update loop (one param fetch serves both), pair table staged in smem.
// NSWEEPS=6 is the convergence floor.

#define C 64
#define TLEN 500
#define NMAT 2560
#define NTRI 2080
#define LDA 65          // stride for sA  (65 % 32 == 1 -> bank = (p1+p2)%32)
#define LDV 66          // stride for sVt (even -> float2-aligned rows)
#define NSWEEPS 6
#define THREADS 256

// Bank-balanced (p,q) labels per round: p | (q<<8)
__device__ int g_pq[63 * 32];

__global__ void prep_pairs_kernel()
{
    int r = threadIdx.x;
    if (r >= 63) return;

    int A[32], B[32];
    A[0] = 63; B[0] = r % 63;
    for (int t = 1; t < 32; t++) {
        A[t] = (r + t) % 63;
        B[t] = (r - t + 63) % 63;
    }
    int inc[32][2];
    int cnt[32];
    for (int v = 0; v < 32; v++) cnt[v] = 0;
    for (int k = 0; k < 32; k++) {
        int u = A[k] & 31, v = B[k] & 31;
        inc[u][cnt[u]++] = k;
        inc[v][cnt[v]++] = k;
    }
    bool done[32];
    for (int k = 0; k < 32; k++) done[k] = false;
    for (int k0 = 0; k0 < 32; k0++) {
        if (done[k0]) continue;
        int e = k0;
        int u = A[e] & 31;
        while (!done[e]) {
            done[e] = true;
            int p, q;
            if ((A[e] & 31) == u) { p = A[e]; q = B[e]; }
            else                  { p = B[e]; q = A[e]; }
            g_pq[r * 32 + e] = p | (q << 8);
            int v = q & 31;
            int e2 = (inc[v][0] == e) ? inc[v][1] : inc[v][0];
            e = e2;
            u = v;
        }
    }
}

__global__ __launch_bounds__(THREADS, 5)
void spd_logm_kernel(const float* __restrict__ xin, float* __restrict__ out)
{
    __shared__ float  sA[C * LDA];        // covariance -> diagonalized -> W
    __shared__ float  sVt[C * LDV];       // eigenvectors TRANSPOSED (row j = eigvec j)
    __shared__ float4 sprm[32];           // (c, s, p, q) per pair
    __shared__ int    s_pqtab[63 * 32];   // staged pair schedule
    __shared__ float  ssum[C];
    __shared__ float  slam[C];

    const int tid = threadIdx.x;
    const int lane = tid & 31;
    const int w8 = tid >> 5;
    const int mat = blockIdx.x;
    const float* __restrict__ xm = xin + (size_t)mat * (C * TLEN);
    float* __restrict__ om = out + (size_t)mat * NTRI;

    // stage pair schedule into shared
#pragma unroll
    for (int it = 0; it < 8; it++) {
        int e = tid + it * THREADS;
        if (e < 63 * 32) s_pqtab[e] = g_pq[e];
    }

    // ---------------- Phase 1: covariance ----------------
    {
        float* xt = sVt;                // 64 x 32 tile, stride 33
        const int ty = tid >> 4;
        const int tx = tid & 15;
        float acc[4][4];
#pragma unroll
        for (int i = 0; i < 4; i++)
#pragma unroll
            for (int j = 0; j < 4; j++) acc[i][j] = 0.0f;
        float rowsum = 0.0f;

        for (int t0 = 0; t0 < TLEN; t0 += 32) {
#pragma unroll
            for (int it = 0; it < 8; it++) {
                int e = tid + it * THREADS;
                int r = e >> 5, cc = e & 31;
                int t = t0 + cc;
                xt[r * 33 + cc] = (t < TLEN) ? xm[r * TLEN + t] : 0.0f;
            }
            __syncthreads();
            if (tid < C) {
#pragma unroll
                for (int cc = 0; cc < 32; cc++) rowsum += xt[tid * 33 + cc];
            }
#pragma unroll 4
            for (int tt = 0; tt < 32; tt++) {
                float a0 = xt[(4 * ty + 0) * 33 + tt];
                float a1 = xt[(4 * ty + 1) * 33 + tt];
                float a2 = xt[(4 * ty + 2) * 33 + tt];
                float a3 = xt[(4 * ty + 3) * 33 + tt];
                float b0 = xt[(4 * tx + 0) * 33 + tt];
                float b1 = xt[(4 * tx + 1) * 33 + tt];
                float b2 = xt[(4 * tx + 2) * 33 + tt];
                float b3 = xt[(4 * tx + 3) * 33 + tt];
                acc[0][0] += a0 * b0; acc[0][1] += a0 * b1; acc[0][2] += a0 * b2; acc[0][3] += a0 * b3;
                acc[1][0] += a1 * b0; acc[1][1] += a1 * b1; acc[1][2] += a1 * b2; acc[1][3] += a1 * b3;
                acc[2][0] += a2 * b0; acc[2][1] += a2 * b1; acc[2][2] += a2 * b2; acc[2][3] += a2 * b3;
                acc[3][0] += a3 * b0; acc[3][1] += a3 * b1; acc[3][2] += a3 * b2; acc[3][3] += a3 * b3;
            }
            __syncthreads();
        }
        if (tid < C) ssum[tid] = rowsum;
        __syncthreads();

        const float invT  = 1.0f / (float)TLEN;
        const float invT1 = 1.0f / (float)(TLEN - 1);
#pragma unroll
        for (int i = 0; i < 4; i++) {
            float si = ssum[4 * ty + i];
#pragma unroll
            for (int j = 0; j < 4; j++) {
                float sj = ssum[4 * tx + j];
                sA[(4 * ty + i) * LDA + (4 * tx + j)] =
                    (acc[i][j] - si * sj * invT) * invT1;
            }
        }
    }
    __syncthreads();

    // Vt = I
#pragma unroll
    for (int it = 0; it < 16; it++) {
        int e = tid + it * THREADS;
        int i = e >> 6, j = e & 63;
        sVt[i * LDV + j] = (i == j) ? 1.0f : 0.0f;
    }
    __syncthreads();

    // ---------------- Phase 2: parallel cyclic Jacobi ----------------
    for (int sweep = 0; sweep < NSWEEPS; sweep++) {
        for (int r = 0; r < 63; r++) {
            if (tid < 32) {
                int pqt = s_pqtab[r * 32 + tid];
                int p = pqt & 255, q = pqt >> 8;
                float app = sA[p * LDA + p];
                float aqq = sA[q * LDA + q];
                float apq = sA[p * LDA + q];
                float cc, ss;
                if (fabsf(apq) > 1e-36f) {
                    float theta = (aqq - app) / (2.0f * apq);
                    float t = copysignf(1.0f, theta) /
                              (fabsf(theta) + sqrtf(theta * theta + 1.0f));
                    cc = rsqrtf(t * t + 1.0f);
                    ss = t * cc;
                } else { cc = 1.0f; ss = 0.0f; }
                sprm[tid] = make_float4(cc, ss,
                                        __int_as_float(p), __int_as_float(q));
            }
            __syncthreads();

            // Merged A + V update. A' = J^T A J on 2x2 blocks (conflict-free:
            // {p mod 32} and {q mod 32} are permutations of 0..31). V rows p1,q1
            // updated float2-wise with the same k1 params.
            {
                const float4 P2 = sprm[lane];
                const int p2 = __float_as_int(P2.z), q2 = __float_as_int(P2.w);
#pragma unroll
                for (int it = 0; it < 4; it++) {
                    const float4 P1 = sprm[w8 + it * 8];   // broadcast
                    const int p1 = __float_as_int(P1.z), q1 = __float_as_int(P1.w);

                    float a00 = sA[p1 * LDA + p2], a01 = sA[p1 * LDA + q2];
                    float a10 = sA[q1 * LDA + p2], a11 = sA[q1 * LDA + q2];
                    float t00 = P1.x * a00 - P1.y * a10, t01 = P1.x * a01 - P1.y * a11;
                    float t10 = P1.y * a00 + P1.x * a10, t11 = P1.y * a01 + P1.x * a11;
                    sA[p1 * LDA + p2] = P2.x * t00 - P2.y * t01;
                    sA[p1 * LDA + q2] = P2.y * t00 + P2.x * t01;
                    sA[q1 * LDA + p2] = P2.x * t10 - P2.y * t11;
                    sA[q1 * LDA + q2] = P2.y * t10 + P2.x * t11;

                    float2* vp2 = (float2*)&sVt[p1 * LDV];
                    float2* vq2 = (float2*)&sVt[q1 * LDV];
                    float2 vp = vp2[lane], vq = vq2[lane];
                    float2 np, nq;
                    np.x = P1.x * vp.x - P1.y * vq.x;
                    np.y = P1.x * vp.y - P1.y * vq.y;
                    nq.x = P1.y * vp.x + P1.x * vq.x;
                    nq.y = P1.y * vp.y + P1.x * vq.y;
                    vp2[lane] = np;
                    vq2[lane] = nq;
                }
            }
            __syncthreads();
        }
    }

    // ---------------- Phase 3: log-eigenvalues + reconstruction ----------------
    if (tid < C) {
        float lam = sA[tid * LDA + tid];
        lam = fmaxf(lam, 1e-10f);
        slam[tid] = logf(lam);
    }
    __syncthreads();
    // W[e][i] = Vt[e][i] * log(lam[e])
#pragma unroll
    for (int it = 0; it < 16; it++) {
        int e2 = tid + it * THREADS;
        int e = e2 >> 6, i = e2 & 63;
        sA[e * LDA + i] = sVt[e * LDV + i] * slam[e];
    }
    __syncthreads();

    // logm[i][j] = sum_e W[e][i] * Vt[e][j], upper triangle only
#pragma unroll
    for (int it = 0; it < 16; it++) {
        int e2 = tid + it * THREADS;
        int i = e2 >> 6, j = e2 & 63;
        if (i <= j) {
            float dot = 0.0f;
#pragma unroll
            for (int e = 0; e < C; e++)
                dot += sA[e * LDA + i] * sVt[e * LDV + j];
            int o = i * C - ((i * (i - 1)) >> 1) + (j - i);
            om[o] = dot;
        }
    }
}

extern "C" void kernel_launch(void* const* d_in, const int* in_sizes, int n_in,
                              void* d_out, int out_size)
{
    const float* x = (const float*)d_in[0];
    float* out = (float*)d_out;
    prep_pairs_kernel<<<1, 64>>>();
    spd_logm_kernel<<<NMAT, THREADS>>>(x, out);
}